// round 2
// baseline (speedup 1.0000x reference)
#include <cuda_runtime.h>

// Problem constants (fixed by the dataset)
#define B_IMG 75
#define N_CLS 5
#define C_DIM 640
#define HW    441
#define KNB   3

// Tiling
#define MTILE 128
#define QTILE 128
#define KC    16
#define MT_TILES ((HW + MTILE - 1) / MTILE)   // 4
#define QT_TILES ((HW + QTILE - 1) / QTILE)   // 4
#define NTHREADS 256
#define NEG_INF  (-1e30f)

// Scratch (no allocations allowed in kernel_launch)
__device__ float g_qn_inv[B_IMG * HW];
__device__ float g_sn_inv[N_CLS * HW];
__device__ float g_partial[B_IMG * N_CLS * MT_TILES];

// ---------------------------------------------------------------------------
// Per-descriptor inverse L2 norms over the channel axis.
// Layout: img[b, c, hw] with hw contiguous -> strided (HW) loads, coalesced
// across threads (consecutive threads = consecutive hw).
// ---------------------------------------------------------------------------
__global__ void norm_kernel(const float* __restrict__ q, const float* __restrict__ S) {
    int idx = blockIdx.x * blockDim.x + threadIdx.x;
    const int nq = B_IMG * HW;
    const int ns = N_CLS * HW;
    if (idx < nq) {
        int b = idx / HW, h = idx - b * HW;
        const float* p = q + (size_t)b * C_DIM * HW + h;
        float s = 0.f;
        #pragma unroll 8
        for (int c = 0; c < C_DIM; ++c) { float v = p[(size_t)c * HW]; s = fmaf(v, v, s); }
        g_qn_inv[idx] = rsqrtf(s);
    } else if (idx < nq + ns) {
        int j = idx - nq;
        int n = j / HW, h = j - n * HW;
        const float* p = S + (size_t)n * C_DIM * HW + h;
        float s = 0.f;
        #pragma unroll 8
        for (int c = 0; c < C_DIM; ++c) { float v = p[(size_t)c * HW]; s = fmaf(v, v, s); }
        g_sn_inv[j] = rsqrtf(s);
    }
}

__device__ __forceinline__ void insert3(float& t0, float& t1, float& t2, float v) {
    if (v > t2) {
        if (v > t1) {
            t2 = t1;
            if (v > t0) { t1 = t0; t0 = v; }
            else        { t1 = v; }
        } else {
            t2 = v;
        }
    }
}

// ---------------------------------------------------------------------------
// Fused GEMM + per-support-column top-3 over query descriptors.
// Grid: (m_tile, class n, image b). Each CTA covers ALL 441 query rows for
// its 128 support columns (so top-3 stays CTA-local), streaming q in 128-row
// tiles. Inner GEMM: 128x128x16 chunks, 8x8 microtile per thread, register
// prefetch of the next K-chunk.
// ---------------------------------------------------------------------------
__global__ __launch_bounds__(NTHREADS) void gemm_top3_kernel(
        const float* __restrict__ q, const float* __restrict__ S) {
    const int mt  = blockIdx.x;   // 0..3
    const int n   = blockIdx.y;   // 0..4
    const int b   = blockIdx.z;   // 0..74
    const int m0  = mt * MTILE;
    const int tid = threadIdx.x;
    const int tx  = tid & 15;
    const int ty  = tid >> 4;

    __shared__ float As[KC][QTILE];
    __shared__ float Bs[KC][MTILE];
    __shared__ float top3s[MTILE][3];      // running top-3 per support column
    __shared__ float cand[16][MTILE][3];   // per-ty local top-3 candidates
    __shared__ float red[NTHREADS];

    if (tid < MTILE) {
        top3s[tid][0] = NEG_INF; top3s[tid][1] = NEG_INF; top3s[tid][2] = NEG_INF;
    }

    const float* qb = q + (size_t)b * C_DIM * HW;
    const float* Sn = S + (size_t)n * C_DIM * HW;

    for (int qt = 0; qt < QT_TILES; ++qt) {
        const int q0 = qt * QTILE;

        float acc[8][8];
        #pragma unroll
        for (int i = 0; i < 8; ++i)
            #pragma unroll
            for (int j = 0; j < 8; ++j) acc[i][j] = 0.f;

        // prefetch K-chunk 0 into registers
        float ra[8], rb[8];
        #pragma unroll
        for (int i = 0; i < 8; ++i) {
            int idx = i * NTHREADS + tid;
            int k = idx >> 7, col = idx & 127;
            int qq = q0 + col;
            int mm = m0 + col;
            ra[i] = (qq < HW) ? qb[(size_t)k * HW + qq] : 0.f;
            rb[i] = (mm < HW) ? Sn[(size_t)k * HW + mm] : 0.f;
        }

        for (int kc0 = 0; kc0 < C_DIM; kc0 += KC) {
            __syncthreads();
            #pragma unroll
            for (int i = 0; i < 8; ++i) {
                int idx = i * NTHREADS + tid;
                int k = idx >> 7, col = idx & 127;
                As[k][col] = ra[i];
                Bs[k][col] = rb[i];
            }
            __syncthreads();

            const int kn = kc0 + KC;
            if (kn < C_DIM) {
                // issue next chunk's global loads early (hidden under FMAs)
                #pragma unroll
                for (int i = 0; i < 8; ++i) {
                    int idx = i * NTHREADS + tid;
                    int k = kn + (idx >> 7), col = idx & 127;
                    int qq = q0 + col;
                    int mm = m0 + col;
                    ra[i] = (qq < HW) ? qb[(size_t)k * HW + qq] : 0.f;
                    rb[i] = (mm < HW) ? Sn[(size_t)k * HW + mm] : 0.f;
                }
            }

            #pragma unroll
            for (int k = 0; k < KC; ++k) {
                float4 a0 = *(const float4*)&As[k][ty * 8];
                float4 a1 = *(const float4*)&As[k][ty * 8 + 4];
                float4 b0 = *(const float4*)&Bs[k][tx * 8];
                float4 b1 = *(const float4*)&Bs[k][tx * 8 + 4];
                float av[8] = {a0.x, a0.y, a0.z, a0.w, a1.x, a1.y, a1.z, a1.w};
                float bv[8] = {b0.x, b0.y, b0.z, b0.w, b1.x, b1.y, b1.z, b1.w};
                #pragma unroll
                for (int i = 0; i < 8; ++i)
                    #pragma unroll
                    for (int j = 0; j < 8; ++j)
                        acc[i][j] = fmaf(av[i], bv[j], acc[i][j]);
            }
        }

        // ---- epilogue for this q-tile: fold qn_inv, local top-3, merge ----
        float qinv[8];
        #pragma unroll
        for (int i = 0; i < 8; ++i) {
            int qrow = q0 + ty * 8 + i;
            qinv[i] = (qrow < HW) ? g_qn_inv[b * HW + qrow] : 0.f;
        }
        #pragma unroll
        for (int j = 0; j < 8; ++j) {
            float t0 = NEG_INF, t1 = NEG_INF, t2 = NEG_INF;
            #pragma unroll
            for (int i = 0; i < 8; ++i) {
                int qrow = q0 + ty * 8 + i;
                if (qrow < HW) insert3(t0, t1, t2, acc[i][j] * qinv[i]);
            }
            int m = tx * 8 + j;
            cand[ty][m][0] = t0;
            cand[ty][m][1] = t1;
            cand[ty][m][2] = t2;
        }
        __syncthreads();
        if (tid < MTILE) {
            float t0 = top3s[tid][0], t1 = top3s[tid][1], t2 = top3s[tid][2];
            #pragma unroll
            for (int r = 0; r < 16; ++r) {
                insert3(t0, t1, t2, cand[r][tid][0]);
                insert3(t0, t1, t2, cand[r][tid][1]);
                insert3(t0, t1, t2, cand[r][tid][2]);
            }
            top3s[tid][0] = t0; top3s[tid][1] = t1; top3s[tid][2] = t2;
        }
        __syncthreads();
    }

    // ---- per-column sum * sn_inv, block-reduce, one partial per CTA ----
    float part = 0.f;
    if (tid < MTILE) {
        int m = m0 + tid;
        if (m < HW) {
            part = (top3s[tid][0] + top3s[tid][1] + top3s[tid][2]) *
                   g_sn_inv[n * HW + m];
        }
    }
    red[tid] = part;
    __syncthreads();
    #pragma unroll
    for (int s = NTHREADS / 2; s > 0; s >>= 1) {
        if (tid < s) red[tid] += red[tid + s];
        __syncthreads();
    }
    if (tid == 0) g_partial[(b * N_CLS + n) * MT_TILES + mt] = red[0];
}

// With qAV_num == 1, exp(mean(log(x), axis=1)) == x, so just sum the m-tile
// partials deterministically.
__global__ void finalize_kernel(float* __restrict__ out) {
    int i = blockIdx.x * blockDim.x + threadIdx.x;
    if (i < B_IMG * N_CLS) {
        float s = 0.f;
        #pragma unroll
        for (int t = 0; t < MT_TILES; ++t) s += g_partial[i * MT_TILES + t];
        out[i] = s;
    }
}

extern "C" void kernel_launch(void* const* d_in, const int* in_sizes, int n_in,
                              void* d_out, int out_size) {
    (void)in_sizes; (void)n_in; (void)out_size;
    const float* q = (const float*)d_in[0];
    const float* S = (const float*)d_in[1];
    // d_in[2..4] are qAV_num / SAV_num / shot_num == 1 (fixed by setup_inputs)
    float* out = (float*)d_out;

    const int ntotal = B_IMG * HW + N_CLS * HW;
    norm_kernel<<<(ntotal + 255) / 256, 256>>>(q, S);

    dim3 grid(MT_TILES, N_CLS, B_IMG);  // 4 x 5 x 75 = 1500 CTAs
    gemm_top3_kernel<<<grid, NTHREADS>>>(q, S);

    finalize_kernel<<<2, 256>>>(out);
}

// round 4
// speedup vs baseline: 4.7593x; 4.7593x over previous
#include <cuda_runtime.h>
#include <cuda_bf16.h>
#include <cstdint>

// ---------------- problem constants ----------------
#define B_IMG 75
#define N_CLS 5
#define C_DIM 640
#define HW    441
#define QPAD  512
#define SPAD  512
#define MT_TILES 4
#define NSTAGES 40          // 4 query tiles x 10 K-chunks of 64
#define NEG_INF (-1e30f)

// ---------------- device scratch ----------------
__device__ __align__(256) __nv_bfloat16 g_qbf[(size_t)B_IMG * QPAD * C_DIM];
__device__ __align__(256) __nv_bfloat16 g_sbf[(size_t)N_CLS * SPAD * C_DIM];
__device__ float g_qn_inv[B_IMG * HW];
__device__ float g_sn_inv[N_CLS * HW];
__device__ float g_partial[B_IMG * N_CLS * MT_TILES];

// ---------------- smem layout (bytes) ----------------
#define A_STRIDE 648                       // elements per row (640 + 8 pad -> 16B skew)
#define A_BYTES  (128 * A_STRIDE * 2)      // 165888
#define B_STRIDE 72                        // 64 + 8 pad
#define B_BYTES  (128 * B_STRIDE * 2)      // 18432
#define A_OFF    0
#define B_OFF0   A_BYTES
#define B_OFF1   (B_OFF0 + B_BYTES)        // 184320
#define QINV_OFF (B_OFF1 + B_BYTES)        // 202752
#define CAND_OFF (QINV_OFF + QPAD * 4)     // 204800
#define RED_OFF  (CAND_OFF + 128 * 8 * 3 * 4) // 217088
#define SMEM_DYN (RED_OFF + 256 * 4)       // 218112

// ---------------- PTX helpers (arch-generic, sm_80+) ----------------
__device__ __forceinline__ uint32_t smem_u32(const void* p) {
    uint32_t a;
    asm("{ .reg .u64 t; cvta.to.shared.u64 t, %1; cvt.u32.u64 %0, t; }" : "=r"(a) : "l"(p));
    return a;
}
__device__ __forceinline__ void cpasync16(uint32_t saddr, const void* g) {
    asm volatile("cp.async.cg.shared.global [%0], [%1], 16;" :: "r"(saddr), "l"(g));
}
__device__ __forceinline__ void cp_commit() { asm volatile("cp.async.commit_group;" ::: "memory"); }

#define LDSM_X4(r0, r1, r2, r3, addr) \
    asm volatile("ldmatrix.sync.aligned.m8n8.x4.shared.b16 {%0,%1,%2,%3}, [%4];" \
                 : "=r"(r0), "=r"(r1), "=r"(r2), "=r"(r3) : "r"(addr))

#define MMA16816(c, a, bb) \
    asm volatile("mma.sync.aligned.m16n8k16.row.col.f32.bf16.bf16.f32 " \
                 "{%0,%1,%2,%3}, {%4,%5,%6,%7}, {%8,%9}, {%0,%1,%2,%3};" \
                 : "+f"((c)[0]), "+f"((c)[1]), "+f"((c)[2]), "+f"((c)[3]) \
                 : "r"((a)[0]), "r"((a)[1]), "r"((a)[2]), "r"((a)[3]), \
                   "r"((bb)[0]), "r"((bb)[1]))

__device__ __forceinline__ void insert3(float& t0, float& t1, float& t2, float v) {
    if (v > t2) {
        if (v > t1) {
            t2 = t1;
            if (v > t0) { t1 = t0; t0 = v; }
            else        { t1 = v; }
        } else {
            t2 = v;
        }
    }
}

// ---------------------------------------------------------------------------
// 1) transpose + convert: fp32 [img][C][HW] -> bf16 [img][512][C] K-major,
//    zero-padded rows (so GEMM loads are unconditional).
// ---------------------------------------------------------------------------
__global__ __launch_bounds__(256) void transpose_bf16_kernel(
        const float* __restrict__ q, const float* __restrict__ S) {
    const int hw_t = blockIdx.x;   // 0..7  (512 rows)
    const int c_t  = blockIdx.y;   // 0..9
    const int img  = blockIdx.z;   // 0..79

    const float* src;
    __nv_bfloat16* dst;
    if (img < B_IMG) {
        src = q + (size_t)img * C_DIM * HW;
        dst = g_qbf + (size_t)img * QPAD * C_DIM;
    } else {
        src = S + (size_t)(img - B_IMG) * C_DIM * HW;
        dst = g_sbf + (size_t)(img - B_IMG) * SPAD * C_DIM;
    }
    const int hw0 = hw_t * 64;
    const int c0  = c_t * 64;

    __shared__ float ts[64][65];
    const int tid = threadIdx.x;

    #pragma unroll
    for (int i = 0; i < 16; ++i) {
        int idx = i * 256 + tid;
        int cl = idx >> 6, hl = idx & 63;
        int hw = hw0 + hl;
        ts[hl][cl] = (hw < HW) ? src[(size_t)(c0 + cl) * HW + hw] : 0.f;
    }
    __syncthreads();

    #pragma unroll
    for (int i = 0; i < 2; ++i) {
        int slot = i * 256 + tid;
        int hl = slot >> 3, ch = slot & 7;
        uint32_t w[4];
        #pragma unroll
        for (int j = 0; j < 4; ++j) {
            __nv_bfloat162 p = __floats2bfloat162_rn(ts[hl][ch * 8 + 2 * j],
                                                     ts[hl][ch * 8 + 2 * j + 1]);
            w[j] = *reinterpret_cast<uint32_t*>(&p);
        }
        *reinterpret_cast<uint4*>(dst + (size_t)(hw0 + hl) * C_DIM + c0 + ch * 8) =
            make_uint4(w[0], w[1], w[2], w[3]);
    }
}

// ---------------------------------------------------------------------------
// 2) inverse L2 norms from the bf16 K-major data (fully coalesced rows).
//    One warp per descriptor; fixed-order shfl reduce -> deterministic.
// ---------------------------------------------------------------------------
__global__ __launch_bounds__(256) void norm_bf16_kernel() {
    const int gw = (blockIdx.x * 256 + threadIdx.x) >> 5;
    const int lane = threadIdx.x & 31;
    const int nq = B_IMG * HW;
    const int ntot = nq + N_CLS * HW;
    if (gw >= ntot) return;

    const __nv_bfloat16* row;
    if (gw < nq) {
        int b = gw / HW, h = gw - b * HW;
        row = g_qbf + ((size_t)b * QPAD + h) * C_DIM;
    } else {
        int j = gw - nq;
        int n = j / HW, h = j - n * HW;
        row = g_sbf + ((size_t)n * SPAD + h) * C_DIM;
    }
    float s = 0.f;
    #pragma unroll
    for (int i = 0; i < 3; ++i) {
        int idx = i * 32 + lane;
        if (idx < 80) {
            uint4 v = *reinterpret_cast<const uint4*>(row + idx * 8);
            const __nv_bfloat162* p = reinterpret_cast<const __nv_bfloat162*>(&v);
            #pragma unroll
            for (int j2 = 0; j2 < 4; ++j2) {
                float2 f = __bfloat1622float2(p[j2]);
                s = fmaf(f.x, f.x, s);
                s = fmaf(f.y, f.y, s);
            }
        }
    }
    #pragma unroll
    for (int o = 16; o > 0; o >>= 1) s += __shfl_down_sync(0xffffffffu, s, o);
    if (lane == 0) {
        float r = rsqrtf(s);
        if (gw < nq) g_qn_inv[gw] = r;
        else         g_sn_inv[gw - nq] = r;
    }
}

// ---------------------------------------------------------------------------
// 3) HMMA GEMM + fused top-3.
//    CTA = (mt, n, b). A = 128 support rows x K=640, resident in smem.
//    B = 512 query rows streamed as 4 tiles x 10 K-chunks (64), double-buffered.
//    8 warps, warp tile 32(M) x 64(N), mma.m16n8k16 bf16 -> fp32.
// ---------------------------------------------------------------------------
__global__ __launch_bounds__(256, 1) void gemm_top3_mma() {
    extern __shared__ char sm[];
    const uint32_t sb = smem_u32(sm);
    const int tid  = threadIdx.x;
    const int lane = tid & 31;
    const int wid  = tid >> 5;
    const int wm   = wid >> 1;        // 0..3 (M)
    const int wn   = wid & 1;         // 0..1 (N)
    const int mt = blockIdx.x, n = blockIdx.y, b = blockIdx.z;

    float* qinvp = reinterpret_cast<float*>(sm + QINV_OFF);
    float* candp = reinterpret_cast<float*>(sm + CAND_OFF);
    float* redp  = reinterpret_cast<float*>(sm + RED_OFF);

    const __nv_bfloat16* Ag = g_sbf + ((size_t)n * SPAD + (size_t)mt * 128) * C_DIM;
    const __nv_bfloat16* Bg = g_qbf + (size_t)b * QPAD * C_DIM;

    for (int i = tid; i < QPAD; i += 256)
        qinvp[i] = (i < HW) ? g_qn_inv[b * HW + i] : 0.f;

    // A: 128 rows x 640 -> smem once (10240 16B chunks)
    #pragma unroll
    for (int it = 0; it < 40; ++it) {
        int idx = it * 256 + tid;
        int row = idx / 80, ch = idx - row * 80;
        cpasync16(sb + A_OFF + row * (A_STRIDE * 2) + ch * 16,
                  Ag + (size_t)row * C_DIM + ch * 8);
    }
    cp_commit();

    // B stage 0 (qt=0, k0=0)
    #pragma unroll
    for (int it = 0; it < 4; ++it) {
        int idx = it * 256 + tid;
        int row = idx >> 3, ch = idx & 7;
        cpasync16(sb + B_OFF0 + row * (B_STRIDE * 2) + ch * 16,
                  Bg + (size_t)row * C_DIM + ch * 8);
    }
    cp_commit();

    float acc[2][8][4];
    #pragma unroll
    for (int fm = 0; fm < 2; ++fm)
        #pragma unroll
        for (int nf = 0; nf < 8; ++nf)
            #pragma unroll
            for (int r = 0; r < 4; ++r) acc[fm][nf][r] = 0.f;

    float t3[2][2][3];
    #pragma unroll
    for (int fm = 0; fm < 2; ++fm)
        #pragma unroll
        for (int h = 0; h < 2; ++h) {
            t3[fm][h][0] = NEG_INF; t3[fm][h][1] = NEG_INF; t3[fm][h][2] = NEG_INF;
        }

    // lane-fixed pieces of ldmatrix addresses
    const uint32_t a_fix = sb + A_OFF +
        (uint32_t)(wm * 32 + (lane & 15)) * (A_STRIDE * 2) + ((lane >> 4) << 4);
    const uint32_t b_lanerow = (uint32_t)(wn * 64 + (lane & 7) + ((lane >> 4) << 3));
    const uint32_t b_fix_off = b_lanerow * (B_STRIDE * 2) + (((lane >> 3) & 1) << 4);

    int qt = 0, kc = 0;
    for (int s = 0; s < NSTAGES; ++s) {
        if (s < NSTAGES - 1) {
            int kc1 = kc + 1, qt1 = qt;
            if (kc1 == 10) { kc1 = 0; qt1 = qt + 1; }
            const uint32_t bb = sb + (((s + 1) & 1) ? B_OFF1 : B_OFF0);
            const __nv_bfloat16* src = Bg + (size_t)(qt1 * 128) * C_DIM + kc1 * 64;
            #pragma unroll
            for (int it = 0; it < 4; ++it) {
                int idx = it * 256 + tid;
                int row = idx >> 3, ch = idx & 7;
                cpasync16(bb + row * (B_STRIDE * 2) + ch * 16,
                          src + (size_t)row * C_DIM + ch * 8);
            }
            cp_commit();
            asm volatile("cp.async.wait_group 1;" ::: "memory");
        } else {
            asm volatile("cp.async.wait_group 0;" ::: "memory");
        }
        __syncthreads();

        const uint32_t abase = a_fix + (uint32_t)kc * 128;   // kc*64 elems * 2B
        const uint32_t bbase = sb + ((s & 1) ? B_OFF1 : B_OFF0) + b_fix_off;

        #pragma unroll
        for (int kk = 0; kk < 4; ++kk) {
            uint32_t a[2][4];
            #pragma unroll
            for (int fm = 0; fm < 2; ++fm)
                LDSM_X4(a[fm][0], a[fm][1], a[fm][2], a[fm][3],
                        abase + (uint32_t)fm * (16 * A_STRIDE * 2) + kk * 32);
            uint32_t bf[8][2];
            #pragma unroll
            for (int nf2 = 0; nf2 < 4; ++nf2) {
                uint32_t r0, r1, r2, r3;
                LDSM_X4(r0, r1, r2, r3,
                        bbase + (uint32_t)nf2 * (16 * B_STRIDE * 2) + kk * 32);
                bf[nf2 * 2][0] = r0; bf[nf2 * 2][1] = r1;
                bf[nf2 * 2 + 1][0] = r2; bf[nf2 * 2 + 1][1] = r3;
            }
            #pragma unroll
            for (int fm = 0; fm < 2; ++fm)
                #pragma unroll
                for (int nf = 0; nf < 8; ++nf)
                    MMA16816(acc[fm][nf], a[fm], bf[nf]);
        }

        if (kc == 9) {
            // per-thread top-3 update for this query tile, then reset acc
            const int colbase = qt * 128 + wn * 64 + (lane & 3) * 2;
            #pragma unroll
            for (int nf = 0; nf < 8; ++nf) {
                #pragma unroll
                for (int h = 0; h < 2; ++h) {
                    #pragma unroll
                    for (int dc = 0; dc < 2; ++dc) {
                        int col = colbase + nf * 8 + dc;
                        if (col < HW) {
                            float v = acc[0][nf][h * 2 + dc] * qinvp[col];
                            insert3(t3[0][h][0], t3[0][h][1], t3[0][h][2], v);
                            float v1 = acc[1][nf][h * 2 + dc] * qinvp[col];
                            insert3(t3[1][h][0], t3[1][h][1], t3[1][h][2], v1);
                        }
                    }
                }
                #pragma unroll
                for (int r = 0; r < 4; ++r) { acc[0][nf][r] = 0.f; acc[1][nf][r] = 0.f; }
            }
        }
        __syncthreads();   // protect B buffer reuse

        if (++kc == 10) { kc = 0; ++qt; }
    }

    // ---- merge per-row top-3 across the 8 holder threads ----
    {
        const int slot = wn * 4 + (lane & 3);
        const int g = lane >> 2;
        #pragma unroll
        for (int fm = 0; fm < 2; ++fm)
            #pragma unroll
            for (int h = 0; h < 2; ++h) {
                int m_local = wm * 32 + fm * 16 + h * 8 + g;
                float* c = &candp[(m_local * 8 + slot) * 3];
                c[0] = t3[fm][h][0]; c[1] = t3[fm][h][1]; c[2] = t3[fm][h][2];
            }
    }
    __syncthreads();

    float part = 0.f;
    if (tid < 128) {
        float t0 = NEG_INF, t1 = NEG_INF, t2 = NEG_INF;
        #pragma unroll
        for (int sl = 0; sl < 8; ++sl) {
            const float* c = &candp[(tid * 8 + sl) * 3];
            insert3(t0, t1, t2, c[0]);
            insert3(t0, t1, t2, c[1]);
            insert3(t0, t1, t2, c[2]);
        }
        int m = mt * 128 + tid;
        if (m < HW) part = (t0 + t1 + t2) * g_sn_inv[n * HW + m];
    }
    redp[tid] = part;
    __syncthreads();
    if (tid < 64) redp[tid] += redp[tid + 64];
    __syncthreads();
    if (tid < 32) {
        float v = redp[tid] + redp[tid + 32];
        #pragma unroll
        for (int o = 16; o > 0; o >>= 1)
            v += __shfl_down_sync(0xffffffffu, v, o);
        if (tid == 0) g_partial[(b * N_CLS + n) * MT_TILES + mt] = v;
    }
}

// ---------------------------------------------------------------------------
// 4) finalize (qAV_num == 1 -> geometric mean is identity)
// ---------------------------------------------------------------------------
__global__ void finalize_kernel(float* __restrict__ out) {
    int i = blockIdx.x * blockDim.x + threadIdx.x;
    if (i < B_IMG * N_CLS) {
        float s = 0.f;
        #pragma unroll
        for (int t = 0; t < MT_TILES; ++t) s += g_partial[i * MT_TILES + t];
        out[i] = s;
    }
}

extern "C" void kernel_launch(void* const* d_in, const int* in_sizes, int n_in,
                              void* d_out, int out_size) {
    (void)in_sizes; (void)n_in; (void)out_size;
    const float* q = (const float*)d_in[0];
    const float* S = (const float*)d_in[1];
    float* out = (float*)d_out;

    static int smem_set = 0;  // idempotent attribute, set once
    if (!smem_set) {
        cudaFuncSetAttribute(gemm_top3_mma,
                             cudaFuncAttributeMaxDynamicSharedMemorySize, SMEM_DYN);
        smem_set = 1;
    }

    transpose_bf16_kernel<<<dim3(8, 10, 80), 256>>>(q, S);

    {
        const int nwarps = B_IMG * HW + N_CLS * HW;
        norm_bf16_kernel<<<(nwarps * 32 + 255) / 256, 256>>>();
    }

    gemm_top3_mma<<<dim3(MT_TILES, N_CLS, B_IMG), 256, SMEM_DYN>>>();

    finalize_kernel<<<2, 256>>>(out);
}